// round 16
// baseline (speedup 1.0000x reference)
#include <cuda_runtime.h>
#include <math.h>
#include <stdint.h>

#define BB 2048
#define LL 1024
#define HH 64
#define TT 16
#define GSTR 68     // sGn fp32 row stride (floats)
#define ASTR 20     // sA row stride (floats): conflict-free scalar fragment loads
#define BSTR 66     // staged B row stride (u32): uint2 loads conflict-free (bijective mod 16)
#define PSTR 68     // sPT row stride (floats): conflict-free transposed dump

// ---------------- precomputed tables ----------------
__device__ float d_K[HH * HH];
__device__ float d_g[HH];
__device__ float d_Gn[HH * HH];      // Gn[v][j] = -a_v * (k_v . k_j)
__device__ float d_r[HH];            // r_v = ||k_v||^2 + 1e-6
__device__ float d_Y[HH * HH];
__device__ float d_Z[HH * HH];
__device__ float d_bias2[HH];

// ---------------- precompute A ----------------
__global__ void __launch_bounds__(128) prekA(
    const float* __restrict__ embed_W, const float* __restrict__ ff_w1, const float* __restrict__ ff_b1,
    const float* __restrict__ ff_w2,   const float* __restrict__ ff_b2, const float* __restrict__ ln_g,
    const float* __restrict__ ln_b,    const float* __restrict__ gate_w1, const float* __restrict__ gate_b1,
    const float* __restrict__ gate_w2, const float* __restrict__ gate_b2)
{
    int v = blockIdx.x;
    int tid = threadIdx.x;
    __shared__ float se[HH];
    __shared__ float sz[2 * HH];
    __shared__ float sk[HH];
    __shared__ float sh[16];
    __shared__ float sred[4];

    if (tid < HH) se[tid] = embed_W[v * HH + tid];
    __syncthreads();

    {
        float z = ff_b1[tid];
        #pragma unroll 8
        for (int i = 0; i < HH; i++) z = fmaf(se[i], ff_w1[i * (2 * HH) + tid], z);
        sz[tid] = fmaxf(z, 0.0f);
    }
    __syncthreads();

    if (tid < HH) {
        float ff = ff_b2[tid];
        #pragma unroll 8
        for (int j = 0; j < 2 * HH; j++) ff = fmaf(sz[j], ff_w2[j * HH + tid], ff);
        float x = se[tid] + ff;

        float s = x;
        #pragma unroll
        for (int o = 16; o > 0; o >>= 1) s += __shfl_xor_sync(0xffffffffu, s, o);
        if ((tid & 31) == 0) sred[tid >> 5] = s;
        __syncwarp();
        __syncthreads();
        float mu = (sred[0] + sred[1]) * (1.0f / HH);

        float d = x - mu;
        float sv = d * d;
        #pragma unroll
        for (int o = 16; o > 0; o >>= 1) sv += __shfl_xor_sync(0xffffffffu, sv, o);
        if ((tid & 31) == 0) sred[2 + (tid >> 5)] = sv;
        __syncwarp();
        __syncthreads();
        float var = (sred[2] + sred[3]) * (1.0f / HH);
        float inv = rsqrtf(var + 1e-5f);
        float k = d * inv * ln_g[tid] + ln_b[tid];
        sk[tid] = k;
        d_K[v * HH + tid] = k;
    }
    __syncthreads();

    if (tid < 16) {
        float hj = gate_b1[tid];
        #pragma unroll 8
        for (int i = 0; i < HH; i++) hj = fmaf(sk[i], gate_w1[i * 16 + tid], hj);
        sh[tid] = fmaxf(hj, 0.0f);
    }
    __syncthreads();
    if (tid == 0) {
        float gz = gate_b2[0];
        #pragma unroll
        for (int j = 0; j < 16; j++) gz = fmaf(sh[j], gate_w2[j], gz);
        d_g[v] = 1.0f / (1.0f + expf(-gz));
    }
}

// ---------------- tf32 split helper ----------------
__device__ __forceinline__ uint32_t tf32b(float x) {
    uint32_t r;
    asm("cvt.rna.tf32.f32 %0, %1;" : "=r"(r) : "f"(x));
    return r;
}

// ---------------- precompute B ----------------
__global__ void __launch_bounds__(64) prekB(
    const float* __restrict__ read_w, const float* __restrict__ read_b,
    const float* __restrict__ out_w,  const float* __restrict__ out_b)
{
    int v = blockIdx.x;
    int u = threadIdx.x;
    __shared__ float skv[HH];
    __shared__ float sdiag;

    skv[u] = d_K[v * HH + u];
    __syncthreads();

    float s = 0.0f;
    #pragma unroll 8
    for (int i = 0; i < HH; i++) s = fmaf(skv[i], d_K[u * HH + i], s);
    if (u == v) sdiag = s;
    __syncthreads();

    float denom = sdiag + 1e-6f;
    float a = d_g[v] / denom;
    d_Gn[v * HH + u] = -a * s;
    if (u == v) d_r[v] = denom;

    float y = 0.0f;
    #pragma unroll 8
    for (int m = 0; m < HH; m++) y = fmaf(read_w[v * HH + m], out_w[m * HH + u], y);
    d_Y[v * HH + u] = y;

    if (v == 0) {
        float b = out_b[u];
        #pragma unroll 8
        for (int m = 0; m < HH; m++) b = fmaf(read_b[m], out_w[m * HH + u], b);
        d_bias2[u] = b;
    }
}

// ---------------- precompute C ----------------
__global__ void __launch_bounds__(64) prekC()
{
    int v = blockIdx.x;
    int n = threadIdx.x;
    __shared__ float skv[HH];
    skv[n] = d_K[v * HH + n];
    __syncthreads();
    float s = 0.0f;
    #pragma unroll 8
    for (int h = 0; h < HH; h++) s = fmaf(skv[h], d_Y[h * HH + n], s);
    d_Z[v * HH + n] = s;
}

// ---------------- mma helper (baseline PTX, sm_80+) ----------------
__device__ __forceinline__ void mma8(float* c,
                                     uint32_t a0, uint32_t a1, uint32_t a2, uint32_t a3,
                                     uint32_t b0, uint32_t b1) {
    asm("mma.sync.aligned.m16n8k8.row.col.f32.tf32.tf32.f32 "
        "{%0,%1,%2,%3},{%4,%5,%6,%7},{%8,%9},{%0,%1,%2,%3};"
        : "+f"(c[0]), "+f"(c[1]), "+f"(c[2]), "+f"(c[3])
        : "r"(a0), "r"(a1), "r"(a2), "r"(a3), "r"(b0), "r"(b1));
}

// ---------------- dynamic shared layout (~50KB -> 4 CTAs/SM) ----------------
struct __align__(16) SMemS {
    float    Gn[HH * GSTR];     // persistent fp32 Gn table             (17408B)
    float    sPT[HH * PSTR];    // P transposed: row = col-of-P         (17408B)
    float    sA[HH * ASTR];     // S^T fp32, row h, col u               (5120B)
    uint32_t sBhi[TT * BSTR];   // staged B hi bits, permuted layout    (4224B)
    uint32_t sBlo[TT * BSTR];   // staged B lo bits                     (4224B)
    float    sC[TT * TT];       // triangular coeffs                    (1024B)
    float    sr[HH];
    int      stok[2][TT];
    short    tri[120];          // (t | u<<8) strictly-lower-triangular LUT
};
#define SMEM_BYTES ((int)sizeof(SMemS))

// ---------------- scan: chunked delta rule, P in mma register fragments ----------------
__global__ void __launch_bounds__(128, 4) scan_mma(const int* __restrict__ seq, float* __restrict__ out)
{
    extern __shared__ __align__(16) char dynsmem[];
    SMemS* sm = (SMemS*)dynsmem;

    int tid = threadIdx.x;
    int warp = tid >> 5, lane = tid & 31;
    int gid = lane >> 2, tig = lane & 3;
    int m0 = warp * 16;
    long b = blockIdx.x;
    const int* seqb = seq + b * LL;

    // persistent fp32 Gn table (smem: per-chunk critical path must never hit L2)
    #pragma unroll 1
    for (int i = tid; i < HH * HH; i += 128) {
        int r = i >> 6, cc = i & 63;
        sm->Gn[r * GSTR + cc] = d_Gn[i];
    }
    if (tid < HH) sm->sr[tid] = d_r[tid];
    if (tid == 0) {
        int e = 0;
        for (int t = 1; t < TT; t++)
            for (int u = 0; u < t; u++) sm->tri[e++] = (short)(t | (u << 8));
    }

    float Cacc[8][4];
    #pragma unroll
    for (int nt = 0; nt < 8; nt++)
        #pragma unroll
        for (int q = 0; q < 4; q++) Cacc[nt][q] = 0.0f;

    const int nsteps = LL - 1;               // 1023
    const int NCH = (nsteps + TT - 1) / TT;  // 64

    // publish chunk-0 tokens; hold chunk-1 tokens in ntok
    int ntok = 0;
    if (tid < TT) {
        int t0 = (tid < nsteps) ? seqb[tid] : 0;
        sm->stok[0][tid] = t0;
        int p = TT + tid;
        ntok = (p < nsteps) ? seqb[p] : 0;
    }
    __syncthreads();

    #pragma unroll 1
    for (int c = 0; c < NCH; c++) {
        int c0 = c * TT;
        int cb = c & 1, nb = cb ^ 1;

        // P3a: ALL warps dump their P rows (pre-update) transposed to sPT. Conflict-free.
        #pragma unroll
        for (int nt = 0; nt < 8; nt++) {
            int r0 = m0 + gid, r1 = r0 + 8;
            int cA = nt * 8 + tig * 2, cB = cA + 1;
            sm->sPT[cA * PSTR + r0] = Cacc[nt][0];
            sm->sPT[cB * PSTR + r0] = Cacc[nt][1];
            sm->sPT[cA * PSTR + r1] = Cacc[nt][2];
            sm->sPT[cB * PSTR + r1] = Cacc[nt][3];
        }
        // P3b: warps 2-3 build C[t][u] = Gn[v_u][v_t] from smem table
        if (warp >= 2) {
            int j = tid - 64;
            #pragma unroll 1
            for (int e = j; e < 120; e += 64) {
                int pk = sm->tri[e];
                int t = pk & 0xff, u = pk >> 8;
                sm->sC[t * TT + u] = sm->Gn[sm->stok[cb][u] * GSTR + sm->stok[cb][t]];
            }
        } else if (tid < TT) {
            // publish NEXT chunk's tokens (write is 2 barriers ahead of its readers)
            sm->stok[nb][tid] = ntok;
            int p = c0 + 2 * TT + tid;
            ntok = (p < nsteps) ? seqb[p] : 0;
        }
        __syncthreads();   // BAR A: sPT + sC ready

        if (warp < 2) {
            // P4: solve; thread h handles component h. 4-way partial chains (reassociated).
            int h = tid;
            float s[TT];
            float rh = sm->sr[h];
            #pragma unroll
            for (int t = 0; t < TT; t++) {
                int vt = sm->stok[cb][t];
                float w = sm->sPT[vt * PSTR + h];
                if (vt == h) w -= rh;
                float p0 = w, p1 = 0.0f, p2 = 0.0f, p3 = 0.0f;
                #pragma unroll
                for (int u = 0; u < TT; u++) {
                    if (u < t) {
                        float pr = sm->sC[t * TT + u] * s[u];
                        if ((u & 3) == 0) p0 += pr;
                        else if ((u & 3) == 1) p1 += pr;
                        else if ((u & 3) == 2) p2 += pr;
                        else p3 += pr;
                    }
                }
                float acc = (p0 + p1) + (p2 + p3);
                if (c0 + t >= nsteps) acc = 0.0f;   // pad steps contribute nothing
                s[t] = acc;
            }
            // stage A = S^T fp32 (row h = component, cols u); split happens in P5
            float4* pa = (float4*)&sm->sA[h * ASTR];
            #pragma unroll
            for (int q = 0; q < 4; q++)
                pa[q] = make_float4(s[4*q], s[4*q+1], s[4*q+2], s[4*q+3]);
        } else {
            // P4b: warps 2-3 split the 16 needed B rows from the smem Gn table.
            // Component j stored at t*BSTR + (j&7)*8 + (j>>3) -> P5 uint2 loads.
            int j = tid - 64;
            int dst = (j & 7) * 8 + (j >> 3);
            #pragma unroll
            for (int t = 0; t < TT; t++) {
                float g = sm->Gn[sm->stok[cb][t] * GSTR + j];
                uint32_t hbits = tf32b(g);
                sm->sBhi[t * BSTR + dst] = hbits;
                sm->sBlo[t * BSTR + dst] = tf32b(g - __uint_as_float(hbits));
            }
        }
        __syncthreads();   // BAR B: A + staged B ready

        // P5: rank-16 update via mma.sync; A split inline, B pre-split + vectorized
        #pragma unroll
        for (int kx = 0; kx < 2; kx++) {
            int u0 = kx * 8 + tig, u4 = u0 + 4;
            float af0 = sm->sA[(m0 + gid)     * ASTR + u0];
            float af1 = sm->sA[(m0 + gid + 8) * ASTR + u0];
            float af2 = sm->sA[(m0 + gid)     * ASTR + u4];
            float af3 = sm->sA[(m0 + gid + 8) * ASTR + u4];
            uint32_t ah0 = tf32b(af0), ah1 = tf32b(af1), ah2 = tf32b(af2), ah3 = tf32b(af3);
            uint32_t al0 = tf32b(af0 - __uint_as_float(ah0));
            uint32_t al1 = tf32b(af1 - __uint_as_float(ah1));
            uint32_t al2 = tf32b(af2 - __uint_as_float(ah2));
            uint32_t al3 = tf32b(af3 - __uint_as_float(ah3));
            const uint2* bh0p = (const uint2*)&sm->sBhi[u0 * BSTR + gid * 8];
            const uint2* bh4p = (const uint2*)&sm->sBhi[u4 * BSTR + gid * 8];
            const uint2* bl0p = (const uint2*)&sm->sBlo[u0 * BSTR + gid * 8];
            const uint2* bl4p = (const uint2*)&sm->sBlo[u4 * BSTR + gid * 8];
            #pragma unroll
            for (int p = 0; p < 4; p++) {
                uint2 h0 = bh0p[p], h4 = bh4p[p], l0 = bl0p[p], l4 = bl4p[p];
                int nt0 = 2 * p, nt1 = 2 * p + 1;
                mma8(Cacc[nt0], ah0, ah1, ah2, ah3, h0.x, h4.x);   // hi*hi
                mma8(Cacc[nt0], ah0, ah1, ah2, ah3, l0.x, l4.x);   // hi*lo
                mma8(Cacc[nt0], al0, al1, al2, al3, h0.x, h4.x);   // lo*hi
                mma8(Cacc[nt1], ah0, ah1, ah2, ah3, h0.y, h4.y);
                mma8(Cacc[nt1], ah0, ah1, ah2, ah3, l0.y, l4.y);
                mma8(Cacc[nt1], al0, al1, al2, al3, h0.y, h4.y);
            }
        }
    }

    // ---- final: dump P once more, read column v_q, logits = P[:,vq]^T Z + bias2 ----
    #pragma unroll
    for (int nt = 0; nt < 8; nt++) {
        int r0 = m0 + gid, r1 = r0 + 8;
        int cA = nt * 8 + tig * 2, cB = cA + 1;
        sm->sPT[cA * PSTR + r0] = Cacc[nt][0];
        sm->sPT[cB * PSTR + r0] = Cacc[nt][1];
        sm->sPT[cA * PSTR + r1] = Cacc[nt][2];
        sm->sPT[cB * PSTR + r1] = Cacc[nt][3];
    }
    __syncthreads();

    if (tid < HH) {
        int n = tid;
        int vq = seqb[LL - 1];
        const float* pcol = &sm->sPT[vq * PSTR];
        float acc = d_bias2[n];
        #pragma unroll 8
        for (int i = 0; i < HH; i++)
            acc = fmaf(pcol[i], d_Z[i * HH + n], acc);
        out[b * HH + n] = acc;
    }
}

// ---------------- launch ----------------
extern "C" void kernel_launch(void* const* d_in, const int* in_sizes, int n_in,
                              void* d_out, int out_size)
{
    const int*   seq     = (const int*)  d_in[0];
    const float* embed_W = (const float*)d_in[1];
    const float* ff_w1   = (const float*)d_in[2];
    const float* ff_b1   = (const float*)d_in[3];
    const float* ff_w2   = (const float*)d_in[4];
    const float* ff_b2   = (const float*)d_in[5];
    const float* ln_g    = (const float*)d_in[6];
    const float* ln_b    = (const float*)d_in[7];
    const float* gate_w1 = (const float*)d_in[8];
    const float* gate_b1 = (const float*)d_in[9];
    const float* gate_w2 = (const float*)d_in[10];
    const float* gate_b2 = (const float*)d_in[11];
    const float* read_w  = (const float*)d_in[12];
    const float* read_b  = (const float*)d_in[13];
    const float* out_w   = (const float*)d_in[14];
    const float* out_b   = (const float*)d_in[15];

    cudaFuncSetAttribute(scan_mma, cudaFuncAttributeMaxDynamicSharedMemorySize, SMEM_BYTES);

    prekA<<<HH, 128>>>(embed_W, ff_w1, ff_b1, ff_w2, ff_b2, ln_g, ln_b,
                       gate_w1, gate_b1, gate_w2, gate_b2);
    prekB<<<HH, HH>>>(read_w, read_b, out_w, out_b);
    prekC<<<HH, HH>>>();
    scan_mma<<<BB, 128, SMEM_BYTES>>>(seq, (float*)d_out);
}

// round 17
// speedup vs baseline: 1.7419x; 1.7419x over previous
#include <cuda_runtime.h>
#include <math.h>
#include <stdint.h>

#define BB 2048
#define LL 1024
#define HH 64
#define TT 16
#define GSTR 68     // sGn fp32 row stride (floats)
#define ASTR 20     // sA row stride (u32): conflict-free A fragment loads
#define BSTR 72     // staged B row stride (u32): bank = 8*tig+gid+8*nt -> all-distinct, 1 wf/load
#define PSTR 68     // sPT row stride (floats): conflict-free transposed dump

// ---------------- precomputed tables ----------------
__device__ float d_K[HH * HH];
__device__ float d_g[HH];
__device__ float d_Gn[HH * HH];      // Gn[v][j] = -a_v * (k_v . k_j)
__device__ float d_r[HH];            // r_v = ||k_v||^2 + 1e-6
__device__ float d_Y[HH * HH];
__device__ float d_Z[HH * HH];
__device__ float d_bias2[HH];

// ---------------- precompute A ----------------
__global__ void __launch_bounds__(128) prekA(
    const float* __restrict__ embed_W, const float* __restrict__ ff_w1, const float* __restrict__ ff_b1,
    const float* __restrict__ ff_w2,   const float* __restrict__ ff_b2, const float* __restrict__ ln_g,
    const float* __restrict__ ln_b,    const float* __restrict__ gate_w1, const float* __restrict__ gate_b1,
    const float* __restrict__ gate_w2, const float* __restrict__ gate_b2)
{
    int v = blockIdx.x;
    int tid = threadIdx.x;
    __shared__ float se[HH];
    __shared__ float sz[2 * HH];
    __shared__ float sk[HH];
    __shared__ float sh[16];
    __shared__ float sred[4];

    if (tid < HH) se[tid] = embed_W[v * HH + tid];
    __syncthreads();

    {
        float z = ff_b1[tid];
        #pragma unroll 8
        for (int i = 0; i < HH; i++) z = fmaf(se[i], ff_w1[i * (2 * HH) + tid], z);
        sz[tid] = fmaxf(z, 0.0f);
    }
    __syncthreads();

    if (tid < HH) {
        float ff = ff_b2[tid];
        #pragma unroll 8
        for (int j = 0; j < 2 * HH; j++) ff = fmaf(sz[j], ff_w2[j * HH + tid], ff);
        float x = se[tid] + ff;

        float s = x;
        #pragma unroll
        for (int o = 16; o > 0; o >>= 1) s += __shfl_xor_sync(0xffffffffu, s, o);
        if ((tid & 31) == 0) sred[tid >> 5] = s;
        __syncwarp();
        __syncthreads();
        float mu = (sred[0] + sred[1]) * (1.0f / HH);

        float d = x - mu;
        float sv = d * d;
        #pragma unroll
        for (int o = 16; o > 0; o >>= 1) sv += __shfl_xor_sync(0xffffffffu, sv, o);
        if ((tid & 31) == 0) sred[2 + (tid >> 5)] = sv;
        __syncwarp();
        __syncthreads();
        float var = (sred[2] + sred[3]) * (1.0f / HH);
        float inv = rsqrtf(var + 1e-5f);
        float k = d * inv * ln_g[tid] + ln_b[tid];
        sk[tid] = k;
        d_K[v * HH + tid] = k;
    }
    __syncthreads();

    if (tid < 16) {
        float hj = gate_b1[tid];
        #pragma unroll 8
        for (int i = 0; i < HH; i++) hj = fmaf(sk[i], gate_w1[i * 16 + tid], hj);
        sh[tid] = fmaxf(hj, 0.0f);
    }
    __syncthreads();
    if (tid == 0) {
        float gz = gate_b2[0];
        #pragma unroll
        for (int j = 0; j < 16; j++) gz = fmaf(sh[j], gate_w2[j], gz);
        d_g[v] = 1.0f / (1.0f + expf(-gz));
    }
}

// ---------------- tf32 split helper ----------------
__device__ __forceinline__ uint32_t tf32b(float x) {
    uint32_t r;
    asm("cvt.rna.tf32.f32 %0, %1;" : "=r"(r) : "f"(x));
    return r;
}

// ---------------- precompute B ----------------
__global__ void __launch_bounds__(64) prekB(
    const float* __restrict__ read_w, const float* __restrict__ read_b,
    const float* __restrict__ out_w,  const float* __restrict__ out_b)
{
    int v = blockIdx.x;
    int u = threadIdx.x;
    __shared__ float skv[HH];
    __shared__ float sdiag;

    skv[u] = d_K[v * HH + u];
    __syncthreads();

    float s = 0.0f;
    #pragma unroll 8
    for (int i = 0; i < HH; i++) s = fmaf(skv[i], d_K[u * HH + i], s);
    if (u == v) sdiag = s;
    __syncthreads();

    float denom = sdiag + 1e-6f;
    float a = d_g[v] / denom;
    d_Gn[v * HH + u] = -a * s;
    if (u == v) d_r[v] = denom;

    float y = 0.0f;
    #pragma unroll 8
    for (int m = 0; m < HH; m++) y = fmaf(read_w[v * HH + m], out_w[m * HH + u], y);
    d_Y[v * HH + u] = y;

    if (v == 0) {
        float b = out_b[u];
        #pragma unroll 8
        for (int m = 0; m < HH; m++) b = fmaf(read_b[m], out_w[m * HH + u], b);
        d_bias2[u] = b;
    }
}

// ---------------- precompute C ----------------
__global__ void __launch_bounds__(64) prekC()
{
    int v = blockIdx.x;
    int n = threadIdx.x;
    __shared__ float skv[HH];
    skv[n] = d_K[v * HH + n];
    __syncthreads();
    float s = 0.0f;
    #pragma unroll 8
    for (int h = 0; h < HH; h++) s = fmaf(skv[h], d_Y[h * HH + n], s);
    d_Z[v * HH + n] = s;
}

// ---------------- mma helper (baseline PTX, sm_80+) ----------------
__device__ __forceinline__ void mma8(float* c,
                                     uint32_t a0, uint32_t a1, uint32_t a2, uint32_t a3,
                                     uint32_t b0, uint32_t b1) {
    asm("mma.sync.aligned.m16n8k8.row.col.f32.tf32.tf32.f32 "
        "{%0,%1,%2,%3},{%4,%5,%6,%7},{%8,%9},{%0,%1,%2,%3};"
        : "+f"(c[0]), "+f"(c[1]), "+f"(c[2]), "+f"(c[3])
        : "r"(a0), "r"(a1), "r"(a2), "r"(a3), "r"(b0), "r"(b1));
}

// ---------------- dynamic shared layout (~55KB -> 4 CTAs/SM, as R13) ----------------
struct __align__(16) SMemS {
    float    Gn[HH * GSTR];     // persistent fp32 Gn table
    float    sPT[HH * PSTR];    // P transposed: row = col-of-P
    uint32_t sAhi[HH * ASTR];   // S^T hi bits, row h, col u
    uint32_t sAlo[HH * ASTR];   // S^T lo bits
    uint32_t sBhi[TT * BSTR];   // staged B hi bits: row t (chunk-local), col n (straight)
    uint32_t sBlo[TT * BSTR];   // staged B lo bits
    float    sC[TT * TT];       // triangular coeffs
    float    sr[HH];
    int      stok[2][TT];
    short    tri[120];          // (t | u<<8) strictly-lower-triangular LUT
};
#define SMEM_BYTES ((int)sizeof(SMemS))

// ---------------- scan: chunked delta rule, P in mma register fragments ----------------
__global__ void __launch_bounds__(128) scan_mma(const int* __restrict__ seq, float* __restrict__ out)
{
    extern __shared__ __align__(16) char dynsmem[];
    SMemS* sm = (SMemS*)dynsmem;

    int tid = threadIdx.x;
    int warp = tid >> 5, lane = tid & 31;
    int gid = lane >> 2, tig = lane & 3;
    int m0 = warp * 16;
    long b = blockIdx.x;
    const int* seqb = seq + b * LL;

    // persistent fp32 table (critical-path data stays in smem — R14 lesson)
    #pragma unroll 1
    for (int i = tid; i < HH * HH; i += 128) {
        int r = i >> 6, cc = i & 63;
        sm->Gn[r * GSTR + cc] = d_Gn[i];
    }
    if (tid < HH) sm->sr[tid] = d_r[tid];
    if (tid == 0) {
        int e = 0;
        for (int t = 1; t < TT; t++)
            for (int u = 0; u < t; u++) sm->tri[e++] = (short)(t | (u << 8));
    }

    float Cacc[8][4];
    #pragma unroll
    for (int nt = 0; nt < 8; nt++)
        #pragma unroll
        for (int q = 0; q < 4; q++) Cacc[nt][q] = 0.0f;

    const int nsteps = LL - 1;               // 1023
    const int NCH = (nsteps + TT - 1) / TT;  // 64

    // publish chunk-0 tokens; hold chunk-1 tokens in ntok
    int ntok = 0;
    if (tid < TT) {
        sm->stok[0][tid] = (tid < nsteps) ? seqb[tid] : 0;
        int p = TT + tid;
        ntok = (p < nsteps) ? seqb[p] : 0;
    }
    __syncthreads();

    #pragma unroll 1
    for (int c = 0; c < NCH; c++) {
        int c0 = c * TT;
        int cb = c & 1, nb = cb ^ 1;

        // P3a: ALL warps dump their P rows (pre-update) transposed to sPT. Conflict-free.
        #pragma unroll
        for (int nt = 0; nt < 8; nt++) {
            int r0 = m0 + gid, r1 = r0 + 8;
            int cA = nt * 8 + tig * 2, cB = cA + 1;
            sm->sPT[cA * PSTR + r0] = Cacc[nt][0];
            sm->sPT[cB * PSTR + r0] = Cacc[nt][1];
            sm->sPT[cA * PSTR + r1] = Cacc[nt][2];
            sm->sPT[cB * PSTR + r1] = Cacc[nt][3];
        }
        // P3b: warps 2-3 build C[t][u] = Gn[v_u][v_t]; warps 0-1 publish NEXT tokens
        if (warp >= 2) {
            int j = tid - 64;
            #pragma unroll 1
            for (int e = j; e < 120; e += 64) {
                int pk = sm->tri[e];
                int t = pk & 0xff, u = pk >> 8;
                sm->sC[t * TT + u] = sm->Gn[sm->stok[cb][u] * GSTR + sm->stok[cb][t]];
            }
        } else if (tid < TT) {
            // write is 2 barriers ahead of its first reader (next chunk's P3b)
            sm->stok[nb][tid] = ntok;
            int p = c0 + 2 * TT + tid;
            ntok = (p < nsteps) ? seqb[p] : 0;
        }
        __syncthreads();   // BAR A: sPT + sC ready

        if (warp < 2) {
            // P4: solve; thread h handles component h. 4-way reassociated chains.
            int h = tid;
            float s[TT];
            float rh = sm->sr[h];
            #pragma unroll
            for (int t = 0; t < TT; t++) {
                int vt = sm->stok[cb][t];
                float w = sm->sPT[vt * PSTR + h];
                if (vt == h) w -= rh;
                float p0 = w, p1 = 0.0f, p2 = 0.0f, p3 = 0.0f;
                #pragma unroll
                for (int u = 0; u < TT; u++) {
                    if (u < t) {
                        float cf = sm->sC[t * TT + u];
                        if ((u & 3) == 0) p0 = fmaf(cf, s[u], p0);
                        else if ((u & 3) == 1) p1 = fmaf(cf, s[u], p1);
                        else if ((u & 3) == 2) p2 = fmaf(cf, s[u], p2);
                        else p3 = fmaf(cf, s[u], p3);
                    }
                }
                float acc = (p0 + p1) + (p2 + p3);
                if (c0 + t >= nsteps) acc = 0.0f;   // pad steps contribute nothing
                s[t] = acc;
            }
            // split 3xTF32 and stage A = S^T (row h = component, cols u)
            uint32_t hb[TT], lb[TT];
            #pragma unroll
            for (int t = 0; t < TT; t++) {
                uint32_t hbits = tf32b(s[t]);
                hb[t] = hbits;
                lb[t] = tf32b(s[t] - __uint_as_float(hbits));
            }
            uint4* ph = (uint4*)&sm->sAhi[h * ASTR];
            uint4* pl = (uint4*)&sm->sAlo[h * ASTR];
            #pragma unroll
            for (int q = 0; q < 4; q++) {
                ph[q] = make_uint4(hb[4*q], hb[4*q+1], hb[4*q+2], hb[4*q+3]);
                pl[q] = make_uint4(lb[4*q], lb[4*q+1], lb[4*q+2], lb[4*q+3]);
            }
        } else {
            // P4b: warps 2-3 split the 16 needed B rows from the smem Gn table.
            // Straight layout (col j): P5 load bank = 8*tig+gid+8*nt -> all-distinct.
            int j = tid - 64;
            #pragma unroll
            for (int t = 0; t < TT; t++) {
                float g = sm->Gn[sm->stok[cb][t] * GSTR + j];
                uint32_t hbits = tf32b(g);
                sm->sBhi[t * BSTR + j] = hbits;
                sm->sBlo[t * BSTR + j] = tf32b(g - __uint_as_float(hbits));
            }
        }
        __syncthreads();   // BAR B: A + staged B ready

        // P5: rank-16 update via mma.sync; A and B fragments pre-split (no cvt, no tokens)
        #pragma unroll
        for (int kx = 0; kx < 2; kx++) {
            int u0 = kx * 8 + tig, u4 = u0 + 4;
            const uint32_t* bh0p = &sm->sBhi[u0 * BSTR + gid];
            const uint32_t* bh4p = &sm->sBhi[u4 * BSTR + gid];
            const uint32_t* bl0p = &sm->sBlo[u0 * BSTR + gid];
            const uint32_t* bl4p = &sm->sBlo[u4 * BSTR + gid];
            uint32_t ah0 = sm->sAhi[(m0 + gid)     * ASTR + u0];
            uint32_t ah1 = sm->sAhi[(m0 + gid + 8) * ASTR + u0];
            uint32_t ah2 = sm->sAhi[(m0 + gid)     * ASTR + u4];
            uint32_t ah3 = sm->sAhi[(m0 + gid + 8) * ASTR + u4];
            uint32_t al0 = sm->sAlo[(m0 + gid)     * ASTR + u0];
            uint32_t al1 = sm->sAlo[(m0 + gid + 8) * ASTR + u0];
            uint32_t al2 = sm->sAlo[(m0 + gid)     * ASTR + u4];
            uint32_t al3 = sm->sAlo[(m0 + gid + 8) * ASTR + u4];
            #pragma unroll
            for (int nt = 0; nt < 8; nt++) {
                uint32_t bh0 = bh0p[nt * 8], bh1 = bh4p[nt * 8];
                uint32_t bl0 = bl0p[nt * 8], bl1 = bl4p[nt * 8];
                mma8(Cacc[nt], ah0, ah1, ah2, ah3, bh0, bh1);   // hi*hi
                mma8(Cacc[nt], ah0, ah1, ah2, ah3, bl0, bl1);   // hi*lo
                mma8(Cacc[nt], al0, al1, al2, al3, bh0, bh1);   // lo*hi
            }
        }
    }

    // ---- final: dump P once more, read column v_q, logits = P[:,vq]^T Z + bias2 ----
    #pragma unroll
    for (int nt = 0; nt < 8; nt++) {
        int r0 = m0 + gid, r1 = r0 + 8;
        int cA = nt * 8 + tig * 2, cB = cA + 1;
        sm->sPT[cA * PSTR + r0] = Cacc[nt][0];
        sm->sPT[cB * PSTR + r0] = Cacc[nt][1];
        sm->sPT[cA * PSTR + r1] = Cacc[nt][2];
        sm->sPT[cB * PSTR + r1] = Cacc[nt][3];
    }
    __syncthreads();

    if (tid < HH) {
        int n = tid;
        int vq = seqb[LL - 1];
        const float* pcol = &sm->sPT[vq * PSTR];
        float acc = d_bias2[n];
        #pragma unroll 8
        for (int i = 0; i < HH; i++)
            acc = fmaf(pcol[i], d_Z[i * HH + n], acc);
        out[b * HH + n] = acc;
    }
}

// ---------------- launch ----------------
extern "C" void kernel_launch(void* const* d_in, const int* in_sizes, int n_in,
                              void* d_out, int out_size)
{
    const int*   seq     = (const int*)  d_in[0];
    const float* embed_W = (const float*)d_in[1];
    const float* ff_w1   = (const float*)d_in[2];
    const float* ff_b1   = (const float*)d_in[3];
    const float* ff_w2   = (const float*)d_in[4];
    const float* ff_b2   = (const float*)d_in[5];
    const float* ln_g    = (const float*)d_in[6];
    const float* ln_b    = (const float*)d_in[7];
    const float* gate_w1 = (const float*)d_in[8];
    const float* gate_b1 = (const float*)d_in[9];
    const float* gate_w2 = (const float*)d_in[10];
    const float* gate_b2 = (const float*)d_in[11];
    const float* read_w  = (const float*)d_in[12];
    const float* read_b  = (const float*)d_in[13];
    const float* out_w   = (const float*)d_in[14];
    const float* out_b   = (const float*)d_in[15];

    cudaFuncSetAttribute(scan_mma, cudaFuncAttributeMaxDynamicSharedMemorySize, SMEM_BYTES);

    prekA<<<HH, 128>>>(embed_W, ff_w1, ff_b1, ff_w2, ff_b2, ln_g, ln_b,
                       gate_w1, gate_b1, gate_w2, gate_b2);
    prekB<<<HH, HH>>>(read_w, read_b, out_w, out_b);
    prekC<<<HH, HH>>>();
    scan_mma<<<BB, 128, SMEM_BYTES>>>(seq, (float*)d_out);
}